// round 16
// baseline (speedup 1.0000x reference)
#include <cuda_runtime.h>
#include <cuda_fp16.h>
#include <cstdint>

#define H        128
#define NROWS    200000
#define TROWS    256
#define NT256    ((NROWS + TROWS - 1) / TROWS)   // 782
#define M_NODES  1000
#define J_NODES  5000
#define SBLOCKS  148                     // 1 block/SM (512 thr), all resident
#define NWTOT    SBLOCKS

// staged row stride: 272B -> 16B-aligned ldmatrix rows, bank shift 4.
#define HSB       272
#define BUFSZ     (TROWS * HSB)          // 69632
#define PART_OFF  (2 * BUFSZ)            // 139264; 2 x 4KB part buffers
#define SMEM_SZ   (PART_OFF + 8192)      // 147456

// precompute tiling: 64 rows per block
#define NT_PM     16                     // ceil(1000/64)
#define NT_PJ     79                     // ceil(5000/64)
#define NT_TOT    95

// ---------------- device scratch ----------------
__device__ __align__(16) __half g_A[M_NODES * H];   // holds A + c (folded)
__device__ __align__(16) __half g_B[J_NODES * H];
__device__ int   g_bar;                  // monotonic ticket barrier
__device__ float g_wmax[NWTOT];
__device__ int   g_warg[NWTOT];
__device__ float g_wZ[NWTOT];
__device__ float g_wS1[NWTOT];

// ---------------- PTX helpers (generic ISA only) ----------------
__device__ __forceinline__ uint32_t smem_u32(const void* p) {
    uint32_t a;
    asm("{ .reg .u64 t; cvta.to.shared.u64 t, %1; cvt.u32.u64 %0, t; }" : "=r"(a) : "l"(p));
    return a;
}
__device__ __forceinline__ void ldsm_x4(uint32_t* r, uint32_t addr) {
    asm volatile("ldmatrix.sync.aligned.m8n8.x4.shared.b16 {%0,%1,%2,%3}, [%4];"
        : "=r"(r[0]), "=r"(r[1]), "=r"(r[2]), "=r"(r[3]) : "r"(addr));
}
__device__ __forceinline__ void mma_f16(float* d, const uint32_t* a, const uint32_t* b) {
    asm volatile("mma.sync.aligned.m16n8k16.row.col.f32.f16.f16.f32 "
        "{%0,%1,%2,%3}, {%4,%5,%6,%7}, {%8,%9}, {%0,%1,%2,%3};"
        : "+f"(d[0]), "+f"(d[1]), "+f"(d[2]), "+f"(d[3])
        : "r"(a[0]), "r"(a[1]), "r"(a[2]), "r"(a[3]), "r"(b[0]), "r"(b[1]));
}
__device__ __forceinline__ uint32_t pack_h2(float lo, float hi) {
    __half2 t = __floats2half2_rn(lo, hi);
    return *(uint32_t*)&t;
}
// fused half2 add + relu: relu(a*1.0 + b)
__device__ __forceinline__ uint32_t h2_addrelu(uint32_t a, uint32_t b) {
    uint32_t r;
    const uint32_t ONE = 0x3C003C00u;
    asm("fma.rn.relu.f16x2 %0, %1, %2, %3;" : "=r"(r) : "r"(a), "r"(ONE), "r"(b));
    return r;
}

// ticket grid barrier: monotonic counter, graph-replay safe (no reset)
__device__ __forceinline__ void grid_bar(int tid) {
    if (tid == 0) {
        __threadfence();
        int ticket = atomicAdd(&g_bar, 1);
        int target = (ticket / SBLOCKS + 1) * SBLOCKS;
        while (*(volatile int*)&g_bar < target) __nanosleep(32);
        __threadfence();
    }
    __syncthreads();
}

// ---------------- fused precompute + score + finalize (persistent) --------
__global__ void __launch_bounds__(512, 1) score_kernel(
        const float* __restrict__ xg,    const float* __restrict__ xm,
        const float* __restrict__ xj,    const float* __restrict__ W0,
        const float* __restrict__ b0,
        const int*   __restrict__ m_ids, const int* __restrict__ job_idx,
        const float* __restrict__ W1,    const float* __restrict__ b1,
        const float* __restrict__ W2,    const float* __restrict__ b2,
        float* __restrict__ out) {
    extern __shared__ char smem[];
    uint32_t sbase = smem_u32(smem);
    float* partbuf = (float*)(smem + PART_OFF);   // 2 x 1024 floats

    int tid  = threadIdx.x;
    int lane = tid & 31;
    int wid  = tid >> 5;          // 0..15
    int g    = lane >> 2;         // 0..7
    int tig  = lane & 3;          // 0..3
    int rh   = wid >> 2;          // 0..3
    int cg   = wid & 3;           // 0..3  (32 outcols each)
    int b    = blockIdx.x;

    uint32_t laneoff = (uint32_t)(((lane & 7) + ((lane >> 3) & 1) * 8) * HSB
                                  + ((lane >> 4) & 1) * 16);

    // ================= PHASE 1: distributed precompute (64 rows/block) ====
    if (b < NT_TOT) {
        const float* src; __half* dst; int r0, cnt, woff;
        bool isA = (b < NT_PM);
        if (isA) { src = xm; dst = g_A; r0 = b * 64;           cnt = M_NODES; woff = 2 * H; }
        else     { src = xj; dst = g_B; r0 = (b - NT_PM) * 64; cnt = J_NODES; woff = 3 * H; }

        uint32_t Fp[8][4][2];
        {
            int n = cg * 32 + g;
            #pragma unroll
            for (int kk = 0; kk < 8; kk++)
                #pragma unroll
                for (int t = 0; t < 4; t++)
                    #pragma unroll
                    for (int e = 0; e < 2; e++) {
                        int k0 = kk * 16 + 2 * tig + e * 8;
                        Fp[kk][t][e] = pack_h2(W0[(woff + k0) * H + n + t * 8],
                                               W0[(woff + k0 + 1) * H + n + t * 8]);
                    }
        }

        float* cpart = partbuf;          // [512]
        float* cfin  = partbuf + 512;    // [128]
        if (isA) {
            int col = tid & 127, hh = tid >> 7;
            float acc = 0.f;
            const float* w = W0 + col;
            #pragma unroll 8
            for (int i = hh * 64; i < hh * 64 + 64; i++) acc += xg[i] * w[i * H];
            cpart[tid] = acc;
        }

        // stage 64 x-rows as fp16 (8 threads/row)
        {
            int row = tid >> 3, p = tid & 7;
            char* rhp = smem + row * HSB;
            int r = r0 + row;
            if (r < cnt) {
                const float4* xr = (const float4*)(src + r * H) + p * 4;
                float4 v0 = xr[0], v1 = xr[1], v2 = xr[2], v3 = xr[3];
                uint4 o0, o1;
                o0.x = pack_h2(v0.x, v0.y); o0.y = pack_h2(v0.z, v0.w);
                o0.z = pack_h2(v1.x, v1.y); o0.w = pack_h2(v1.z, v1.w);
                o1.x = pack_h2(v2.x, v2.y); o1.y = pack_h2(v2.z, v2.w);
                o1.z = pack_h2(v3.x, v3.y); o1.w = pack_h2(v3.z, v3.w);
                *(uint4*)(rhp + p * 32)      = o0;
                *(uint4*)(rhp + p * 32 + 16) = o1;
            } else {
                uint4 zz = make_uint4(0u, 0u, 0u, 0u);
                *(uint4*)(rhp + p * 32)      = zz;
                *(uint4*)(rhp + p * 32 + 16) = zz;
            }
        }
        __syncthreads();
        if (isA && tid < 128)
            cfin[tid] = cpart[tid] + cpart[tid + 128] + cpart[tid + 256]
                      + cpart[tid + 384] + b0[tid];
        __syncthreads();

        {
            float d[4][4];
            #pragma unroll
            for (int t = 0; t < 4; t++)
                d[t][0] = d[t][1] = d[t][2] = d[t][3] = 0.f;
            uint32_t ahi = sbase + (uint32_t)(rh * 16 * HSB) + laneoff;
            #pragma unroll
            for (int kk = 0; kk < 8; kk++) {
                uint32_t ah[4];
                ldsm_x4(ah, ahi + kk * 32);
                #pragma unroll
                for (int t = 0; t < 4; t++) mma_f16(d[t], ah, Fp[kk][t]);
            }
            int row0 = r0 + rh * 16 + g, row1 = row0 + 8;
            #pragma unroll
            for (int t = 0; t < 4; t++) {
                int c0 = cg * 32 + t * 8 + 2 * tig;
                float a0 = 0.f, a1 = 0.f;
                if (isA) { a0 = cfin[c0]; a1 = cfin[c0 + 1]; }
                if (row0 < cnt)
                    *(uint32_t*)&dst[row0 * H + c0] = pack_h2(d[t][0] + a0, d[t][1] + a1);
                if (row1 < cnt)
                    *(uint32_t*)&dst[row1 * H + c0] = pack_h2(d[t][2] + a0, d[t][3] + a1);
            }
        }
        __syncthreads();
    }

    // W1 fragments: warp owns 32 outcols (4 n-tiles)
    uint32_t Fh[8][4][2];
    {
        int n = cg * 32 + g;
        #pragma unroll
        for (int kk = 0; kk < 8; kk++)
            #pragma unroll
            for (int t = 0; t < 4; t++)
                #pragma unroll
                for (int e = 0; e < 2; e++) {
                    int k0 = kk * 16 + 2 * tig + e * 8;
                    Fh[kk][t][e] = pack_h2(W1[k0 * H + n + t * 8],
                                           W1[(k0 + 1) * H + n + t * 8]);
                }
    }
    float b1c[4][2], w2c[4][2];
    #pragma unroll
    for (int t = 0; t < 4; t++)
        #pragma unroll
        for (int e = 0; e < 2; e++) {
            int col = cg * 32 + t * 8 + 2 * tig + e;
            b1c[t][e] = b1[col];
            w2c[t][e] = W2[col];
        }
    float b2v = b2[0];

    // ================= grid barrier #1 ==================================
    grid_bar(tid);

    // ================= PHASE 2: pipelined score mainloop ================
    // stage: 4 threads/row (conflict-free), 2 passes of 128 rows
    #define STAGE(BOFF, TILE)                                                \
    do {                                                                     \
        int rowb = tid >> 2, q = tid & 3;                                    \
        _Pragma("unroll")                                                    \
        for (int pass = 0; pass < 2; pass++) {                               \
            int row = pass * 128 + rowb;                                     \
            char* rhp = smem + (BOFF) + row * HSB;                           \
            int grow = (TILE) * TROWS + row;                                 \
            if (grow < NROWS) {                                              \
                int m = m_ids[grow], j = job_idx[grow];                      \
                const uint4* Am = (const uint4*)(g_A + m * H) + q * 4;       \
                const uint4* Bj = (const uint4*)(g_B + j * H) + q * 4;       \
                _Pragma("unroll")                                            \
                for (int c = 0; c < 4; c++) {                                \
                    uint4 a = Am[c], bb = Bj[c], o;                          \
                    o.x = h2_addrelu(a.x, bb.x);                             \
                    o.y = h2_addrelu(a.y, bb.y);                             \
                    o.z = h2_addrelu(a.z, bb.z);                             \
                    o.w = h2_addrelu(a.w, bb.w);                             \
                    *(uint4*)(rhp + (q * 4 + c) * 16) = o;                   \
                }                                                            \
            } else {                                                         \
                uint4 zz = make_uint4(0u, 0u, 0u, 0u);                       \
                _Pragma("unroll")                                            \
                for (int c = 0; c < 4; c++)                                  \
                    *(uint4*)(rhp + (q * 4 + c) * 16) = zz;                  \
            }                                                                \
        }                                                                    \
    } while (0)

    float mx = -3.402823466e38f, Z = 0.f, S1 = 0.f;
    int   arg = 0x7fffffff;

    int tile = b;
    int cur = 0, par = 0;
    if (tile < NT256) { STAGE(0, tile); }
    __syncthreads();

    for (; tile < NT256; tile += SBLOCKS) {
        float* pp = partbuf + par * 1024;
        uint32_t boff = (uint32_t)cur * BUFSZ;

        // mma: warp does 4 m-tiles x 4 n-tiles over current buffer
        #pragma unroll
        for (int mi = 0; mi < 4; mi++) {
            int mt = rh * 4 + mi;
            float d[4][4];
            #pragma unroll
            for (int t = 0; t < 4; t++)
                d[t][0] = d[t][1] = d[t][2] = d[t][3] = 0.f;
            uint32_t ahi = sbase + boff + (uint32_t)(mt * 16 * HSB) + laneoff;
            #pragma unroll
            for (int kk = 0; kk < 8; kk++) {
                uint32_t ah[4];
                ldsm_x4(ah, ahi + kk * 32);
                #pragma unroll
                for (int t = 0; t < 4; t++) mma_f16(d[t], ah, Fh[kk][t]);
            }
            float sg = 0.f, sh = 0.f;
            #pragma unroll
            for (int t = 0; t < 4; t++) {
                sg += fmaxf(d[t][0] + b1c[t][0], 0.f) * w2c[t][0]
                    + fmaxf(d[t][1] + b1c[t][1], 0.f) * w2c[t][1];
                sh += fmaxf(d[t][2] + b1c[t][0], 0.f) * w2c[t][0]
                    + fmaxf(d[t][3] + b1c[t][1], 0.f) * w2c[t][1];
            }
            sg += __shfl_xor_sync(0xffffffffu, sg, 1);
            sg += __shfl_xor_sync(0xffffffffu, sg, 2);
            sh += __shfl_xor_sync(0xffffffffu, sh, 1);
            sh += __shfl_xor_sync(0xffffffffu, sh, 2);
            if (tig == 0) {
                pp[cg * 256 + mt * 16 + g]     = sg;
                pp[cg * 256 + mt * 16 + 8 + g] = sh;
            }
        }

        // stage next tile into other buffer (LDG hides under sync/softmax)
        int ntile = tile + SBLOCKS;
        if (ntile < NT256) { STAGE((cur ^ 1) * BUFSZ, ntile); }

        __syncthreads();   // single sync per tile

        // per-row score + online softmax (threads 0..255, one row each)
        if (tid < 256) {
            int grow = tile * TROWS + tid;
            if (grow < NROWS) {
                float s = b2v + pp[tid] + pp[256 + tid]
                              + pp[512 + tid] + pp[768 + tid];
                if (s > mx) {
                    float dd = fmaxf(mx - s, -87.f);
                    float e = expf(dd);
                    S1 = e * (S1 + dd * Z);
                    Z  = e * Z + 1.f;
                    mx = s;
                    arg = grow;
                } else {
                    float t = fmaxf(s - mx, -87.f);
                    float e = expf(t);
                    Z  += e;
                    S1 += t * e;
                }
            }
        }
        cur ^= 1; par ^= 1;
    }
    #undef STAGE
    __syncthreads();

    // block merge of per-thread softmax states (threads 0..255 hold state)
    float* smx = partbuf;          // [256]
    float* sZ  = partbuf + 256;
    float* sS1 = partbuf + 512;
    int*   sarg = (int*)(partbuf + 768);
    if (tid < 256) { smx[tid] = mx; sZ[tid] = Z; sS1[tid] = S1; sarg[tid] = arg; }
    __syncthreads();
    for (int s = 128; s; s >>= 1) {
        if (tid < s) {
            float qm = smx[tid + s], qZ = sZ[tid + s], qS = sS1[tid + s];
            int   qa = sarg[tid + s];
            if (qm > smx[tid] || (qm == smx[tid] && qa < sarg[tid])) {
                float d = fmaxf(smx[tid] - qm, -87.f);
                float e = expf(d);
                float Zo = sZ[tid], S1o = sS1[tid];
                sZ[tid]  = qZ + e * Zo;
                sS1[tid] = qS + e * (S1o + d * Zo);
                smx[tid] = qm; sarg[tid] = qa;
            } else {
                float d = fmaxf(qm - smx[tid], -87.f);
                float e = expf(d);
                sZ[tid]  += e * qZ;
                sS1[tid] += e * (qS + d * qZ);
            }
        }
        __syncthreads();
    }
    if (tid == 0) {
        g_wmax[b] = smx[0];
        g_warg[b] = sarg[0];
        g_wZ[b]   = sZ[0];
        g_wS1[b]  = sS1[0];
    }

    // ================= grid barrier #2 + inline finalize ================
    grid_bar(tid);
    if (b != 0) return;

    float fmx = -3.402823466e38f, fZ = 0.f, fS1 = 0.f;
    int   farg = 0x7fffffff;
    if (tid < 128) {
        for (int i = tid; i < NWTOT; i += 128) {
            float qm = g_wmax[i], qZ = g_wZ[i], qS = g_wS1[i];
            int   qa = g_warg[i];
            if (qm > fmx || (qm == fmx && qa < farg)) {
                float d = fmaxf(fmx - qm, -87.f);
                float e = expf(d);
                float Zo = fZ, S1o = fS1;
                fZ  = qZ + e * Zo;
                fS1 = qS + e * (S1o + d * Zo);
                fmx = qm; farg = qa;
            } else {
                float d = fmaxf(qm - fmx, -87.f);
                float e = expf(d);
                fZ  += e * qZ;
                fS1 += e * (qS + d * qZ);
            }
        }
    }
    __syncthreads();
    if (tid < 128) { smx[tid] = fmx; sarg[tid] = farg; sZ[tid] = fZ; sS1[tid] = fS1; }
    __syncthreads();
    for (int s = 64; s; s >>= 1) {
        if (tid < s) {
            float qm = smx[tid + s], qZ = sZ[tid + s], qS = sS1[tid + s];
            int   qa = sarg[tid + s];
            if (qm > smx[tid] || (qm == smx[tid] && qa < sarg[tid])) {
                float d = fmaxf(smx[tid] - qm, -87.f);
                float e = expf(d);
                float Zo = sZ[tid], S1o = sS1[tid];
                sZ[tid]  = qZ + e * Zo;
                sS1[tid] = qS + e * (S1o + d * Zo);
                smx[tid] = qm; sarg[tid] = qa;
            } else {
                float d = fmaxf(qm - smx[tid], -87.f);
                float e = expf(d);
                sZ[tid]  += e * qZ;
                sS1[tid] += e * (qS + d * qZ);
            }
        }
        __syncthreads();
    }
    if (tid == 0) {
        float Zf = sZ[0], S1f = sS1[0];
        float logZ = logf(Zf);
        out[0] = (float)sarg[0];
        out[1] = 1.0f / Zf;          // p[idx]  (t=0 at argmax)
        out[2] = -logZ;              // logp[idx]
        out[3] = logZ - S1f / Zf;    // entropy
    }
}

// ---------------- launch ----------------
extern "C" void kernel_launch(void* const* d_in, const int* in_sizes, int n_in,
                              void* d_out, int out_size) {
    const float* x_graph = (const float*)d_in[0];
    const float* x_m     = (const float*)d_in[1];
    const float* x_job   = (const float*)d_in[2];
    const int*   m_ids   = (const int*)  d_in[3];
    const int*   job_idx = (const int*)  d_in[4];
    const float* W0      = (const float*)d_in[5];
    const float* b0      = (const float*)d_in[6];
    const float* W1      = (const float*)d_in[7];
    const float* b1      = (const float*)d_in[8];
    const float* W2      = (const float*)d_in[9];
    const float* b2      = (const float*)d_in[10];
    float* out = (float*)d_out;

    cudaFuncSetAttribute(score_kernel,
                         cudaFuncAttributeMaxDynamicSharedMemorySize, SMEM_SZ);

    score_kernel<<<SBLOCKS, 512, SMEM_SZ>>>(x_graph, x_m, x_job, W0, b0,
                                            m_ids, job_idx, W1, b1, W2, b2, out);
}

// round 17
// speedup vs baseline: 1.0224x; 1.0224x over previous
#include <cuda_runtime.h>
#include <cuda_fp16.h>
#include <cstdint>

#define H        128
#define NROWS    200000
#define NTILES   ((NROWS + 127) / 128)   // 1563
#define M_NODES  1000
#define J_NODES  5000
#define SBLOCKS  148                     // 1 block/SM (512 thr), all resident
#define NWTOT    SBLOCKS

// staged row stride: 272B -> 16B-aligned ldmatrix rows, bank shift 4.
#define HSB       272
#define PART_OFF  (128 * HSB)            // 34816 (scratch: 1024 floats)
#define SB1_OFF   (PART_OFF + 4096)      // b1 copy  [128]
#define SW2_OFF   (SB1_OFF + 512)        // W2 copy  [128]
#define SMEM_SZ   (SW2_OFF + 512)        // 39936

// precompute tiling: 64 rows per block
#define NT_PM     16                     // ceil(1000/64)
#define NT_PJ     79                     // ceil(5000/64)
#define NT_TOT    95

// ---------------- device scratch ----------------
__device__ __align__(16) __half g_A[M_NODES * H];   // holds A + c (folded)
__device__ __align__(16) __half g_B[J_NODES * H];
__device__ int   g_bar;                  // monotonic ticket barrier
__device__ float g_wmax[NWTOT];
__device__ int   g_warg[NWTOT];
__device__ float g_wZ[NWTOT];
__device__ float g_wS1[NWTOT];

// ---------------- PTX helpers (generic ISA only) ----------------
__device__ __forceinline__ uint32_t smem_u32(const void* p) {
    uint32_t a;
    asm("{ .reg .u64 t; cvta.to.shared.u64 t, %1; cvt.u32.u64 %0, t; }" : "=r"(a) : "l"(p));
    return a;
}
__device__ __forceinline__ void ldsm_x4(uint32_t* r, uint32_t addr) {
    asm volatile("ldmatrix.sync.aligned.m8n8.x4.shared.b16 {%0,%1,%2,%3}, [%4];"
        : "=r"(r[0]), "=r"(r[1]), "=r"(r[2]), "=r"(r[3]) : "r"(addr));
}
__device__ __forceinline__ void mma_f16(float* d, const uint32_t* a, const uint32_t* b) {
    asm volatile("mma.sync.aligned.m16n8k16.row.col.f32.f16.f16.f32 "
        "{%0,%1,%2,%3}, {%4,%5,%6,%7}, {%8,%9}, {%0,%1,%2,%3};"
        : "+f"(d[0]), "+f"(d[1]), "+f"(d[2]), "+f"(d[3])
        : "r"(a[0]), "r"(a[1]), "r"(a[2]), "r"(a[3]), "r"(b[0]), "r"(b[1]));
}
__device__ __forceinline__ uint32_t pack_h2(float lo, float hi) {
    __half2 t = __floats2half2_rn(lo, hi);
    return *(uint32_t*)&t;
}
// fused half2 add + relu: relu(a*1.0 + b)
__device__ __forceinline__ uint32_t h2_addrelu(uint32_t a, uint32_t b) {
    uint32_t r;
    const uint32_t ONE = 0x3C003C00u;
    asm("fma.rn.relu.f16x2 %0, %1, %2, %3;" : "=r"(r) : "r"(a), "r"(ONE), "r"(b));
    return r;
}

// ticket grid barrier: monotonic counter, graph-replay safe (no reset)
__device__ __forceinline__ void grid_bar(int tid) {
    if (tid == 0) {
        __threadfence();
        int ticket = atomicAdd(&g_bar, 1);
        int target = (ticket / SBLOCKS + 1) * SBLOCKS;
        while (*(volatile int*)&g_bar < target) __nanosleep(32);
        __threadfence();
    }
    __syncthreads();
}

// ---------------- fused precompute + score + finalize (persistent) --------
__global__ void __launch_bounds__(512, 1) score_kernel(
        const float* __restrict__ xg,    const float* __restrict__ xm,
        const float* __restrict__ xj,    const float* __restrict__ W0,
        const float* __restrict__ b0,
        const int*   __restrict__ m_ids, const int* __restrict__ job_idx,
        const float* __restrict__ W1,    const float* __restrict__ b1,
        const float* __restrict__ W2,    const float* __restrict__ b2,
        float* __restrict__ out) {
    extern __shared__ char smem[];
    uint32_t sbase = smem_u32(smem);
    float* scratch = (float*)(smem + PART_OFF);   // 1024 floats
    float* sb1 = (float*)(smem + SB1_OFF);
    float* sw2 = (float*)(smem + SW2_OFF);

    int tid  = threadIdx.x;
    int lane = tid & 31;
    int wid  = tid >> 5;          // 0..15
    int g    = lane >> 2;         // 0..7
    int tig  = lane & 3;          // 0..3
    int rh   = wid >> 2;          // 0..3  (m-tile pair group)
    int cg   = wid & 3;           // 0..3  (32 outcols each)
    int b    = blockIdx.x;

    uint32_t laneoff = (uint32_t)(((lane & 7) + ((lane >> 3) & 1) * 8) * HSB
                                  + ((lane >> 4) & 1) * 16);

    // ================= PHASE 1: distributed precompute (64 rows/block) ====
    if (b < NT_TOT) {
        const float* src; __half* dst; int r0, cnt, woff;
        bool isA = (b < NT_PM);
        if (isA) { src = xm; dst = g_A; r0 = b * 64;           cnt = M_NODES; woff = 2 * H; }
        else     { src = xj; dst = g_B; r0 = (b - NT_PM) * 64; cnt = J_NODES; woff = 3 * H; }

        uint32_t Fp[8][4][2];
        {
            int n = cg * 32 + g;
            #pragma unroll
            for (int kk = 0; kk < 8; kk++)
                #pragma unroll
                for (int t = 0; t < 4; t++)
                    #pragma unroll
                    for (int e = 0; e < 2; e++) {
                        int k0 = kk * 16 + 2 * tig + e * 8;
                        Fp[kk][t][e] = pack_h2(W0[(woff + k0) * H + n + t * 8],
                                               W0[(woff + k0 + 1) * H + n + t * 8]);
                    }
        }

        float* cpart = scratch;          // [512]
        float* cfin  = scratch + 512;    // [128]
        if (isA) {
            int col = tid & 127, hh = tid >> 7;
            float acc = 0.f;
            const float* w = W0 + col;
            #pragma unroll 8
            for (int i = hh * 64; i < hh * 64 + 64; i++) acc += xg[i] * w[i * H];
            cpart[tid] = acc;
        }

        // stage 64 x-rows as fp16 (8 threads/row)
        {
            int row = tid >> 3, p = tid & 7;
            char* rhp = smem + row * HSB;
            int r = r0 + row;
            if (r < cnt) {
                const float4* xr = (const float4*)(src + r * H) + p * 4;
                float4 v0 = xr[0], v1 = xr[1], v2 = xr[2], v3 = xr[3];
                uint4 o0, o1;
                o0.x = pack_h2(v0.x, v0.y); o0.y = pack_h2(v0.z, v0.w);
                o0.z = pack_h2(v1.x, v1.y); o0.w = pack_h2(v1.z, v1.w);
                o1.x = pack_h2(v2.x, v2.y); o1.y = pack_h2(v2.z, v2.w);
                o1.z = pack_h2(v3.x, v3.y); o1.w = pack_h2(v3.z, v3.w);
                *(uint4*)(rhp + p * 32)      = o0;
                *(uint4*)(rhp + p * 32 + 16) = o1;
            } else {
                uint4 zz = make_uint4(0u, 0u, 0u, 0u);
                *(uint4*)(rhp + p * 32)      = zz;
                *(uint4*)(rhp + p * 32 + 16) = zz;
            }
        }
        __syncthreads();
        if (isA && tid < 128)
            cfin[tid] = cpart[tid] + cpart[tid + 128] + cpart[tid + 256]
                      + cpart[tid + 384] + b0[tid];
        __syncthreads();

        {
            float d[4][4];
            #pragma unroll
            for (int t = 0; t < 4; t++)
                d[t][0] = d[t][1] = d[t][2] = d[t][3] = 0.f;
            uint32_t ahi = sbase + (uint32_t)(rh * 16 * HSB) + laneoff;
            #pragma unroll
            for (int kk = 0; kk < 8; kk++) {
                uint32_t ah[4];
                ldsm_x4(ah, ahi + kk * 32);
                #pragma unroll
                for (int t = 0; t < 4; t++) mma_f16(d[t], ah, Fp[kk][t]);
            }
            int row0 = r0 + rh * 16 + g, row1 = row0 + 8;
            #pragma unroll
            for (int t = 0; t < 4; t++) {
                int c0 = cg * 32 + t * 8 + 2 * tig;
                float a0 = 0.f, a1 = 0.f;
                if (isA) { a0 = cfin[c0]; a1 = cfin[c0 + 1]; }
                if (row0 < cnt)
                    *(uint32_t*)&dst[row0 * H + c0] = pack_h2(d[t][0] + a0, d[t][1] + a1);
                if (row1 < cnt)
                    *(uint32_t*)&dst[row1 * H + c0] = pack_h2(d[t][2] + a0, d[t][3] + a1);
            }
        }
        __syncthreads();
    }

    // W1 fragments: warp owns 32 outcols (4 n-tiles)
    uint32_t Fh[8][4][2];
    {
        int n = cg * 32 + g;
        #pragma unroll
        for (int kk = 0; kk < 8; kk++)
            #pragma unroll
            for (int t = 0; t < 4; t++)
                #pragma unroll
                for (int e = 0; e < 2; e++) {
                    int k0 = kk * 16 + 2 * tig + e * 8;
                    Fh[kk][t][e] = pack_h2(W1[k0 * H + n + t * 8],
                                           W1[(k0 + 1) * H + n + t * 8]);
                }
    }
    // epilogue constants live in smem (frees 16 regs for dual-mt accumulators)
    if (tid < 128) { sb1[tid] = b1[tid]; sw2[tid] = W2[tid]; }
    float b2v = b2[0];

    // ================= grid barrier #1 ==================================
    grid_bar(tid);

    // ================= PHASE 2: score mainloop ==========================
    float mx = -3.402823466e38f, Z = 0.f, S1 = 0.f;
    int   arg = 0x7fffffff;
    float* part = scratch;    // [4][128]

    for (int tile = b; tile < NTILES; tile += SBLOCKS) {
        int tbase = tile * 128;

        // gather + fused fma.relu fp16 staging: 4 threads/row (conflict-free)
        {
            int row = tid >> 2, q = tid & 3;
            char* rhp = smem + row * HSB;
            int grow = tbase + row;
            if (grow < NROWS) {
                int m = m_ids[grow], j = job_idx[grow];
                const uint4* Am = (const uint4*)(g_A + m * H) + q * 4;
                const uint4* Bj = (const uint4*)(g_B + j * H) + q * 4;
                #pragma unroll
                for (int c = 0; c < 4; c++) {
                    uint4 a = Am[c], bb = Bj[c], o;
                    o.x = h2_addrelu(a.x, bb.x);
                    o.y = h2_addrelu(a.y, bb.y);
                    o.z = h2_addrelu(a.z, bb.z);
                    o.w = h2_addrelu(a.w, bb.w);
                    *(uint4*)(rhp + (q * 4 + c) * 16) = o;
                }
            } else {
                uint4 zz = make_uint4(0u, 0u, 0u, 0u);
                #pragma unroll
                for (int c = 0; c < 4; c++) *(uint4*)(rhp + (q * 4 + c) * 16) = zz;
            }
        }
        __syncthreads();

        // mma: BOTH m-tiles interleaved — 2 ldsm + 8 independent mma in flight
        {
            int mt0 = rh * 2, mt1 = mt0 + 1;
            float d0[4][4], d1[4][4];
            #pragma unroll
            for (int t = 0; t < 4; t++) {
                d0[t][0] = d0[t][1] = d0[t][2] = d0[t][3] = 0.f;
                d1[t][0] = d1[t][1] = d1[t][2] = d1[t][3] = 0.f;
            }
            uint32_t ahi0 = sbase + (uint32_t)(mt0 * 16 * HSB) + laneoff;
            uint32_t ahi1 = sbase + (uint32_t)(mt1 * 16 * HSB) + laneoff;
            #pragma unroll
            for (int kk = 0; kk < 8; kk++) {
                uint32_t a0[4], a1[4];
                ldsm_x4(a0, ahi0 + kk * 32);
                ldsm_x4(a1, ahi1 + kk * 32);
                #pragma unroll
                for (int t = 0; t < 4; t++) mma_f16(d0[t], a0, Fh[kk][t]);
                #pragma unroll
                for (int t = 0; t < 4; t++) mma_f16(d1[t], a1, Fh[kk][t]);
            }
            // epilogue for both m-tiles; constants from smem
            #pragma unroll
            for (int half = 0; half < 2; half++) {
                float (*d)[4] = half ? d1 : d0;
                int mt = half ? mt1 : mt0;
                float sg = 0.f, sh = 0.f;
                #pragma unroll
                for (int t = 0; t < 4; t++) {
                    int c0 = cg * 32 + t * 8 + 2 * tig;
                    float bb0 = sb1[c0], bb1 = sb1[c0 + 1];
                    float ww0 = sw2[c0], ww1 = sw2[c0 + 1];
                    sg += fmaxf(d[t][0] + bb0, 0.f) * ww0
                        + fmaxf(d[t][1] + bb1, 0.f) * ww1;
                    sh += fmaxf(d[t][2] + bb0, 0.f) * ww0
                        + fmaxf(d[t][3] + bb1, 0.f) * ww1;
                }
                sg += __shfl_xor_sync(0xffffffffu, sg, 1);
                sg += __shfl_xor_sync(0xffffffffu, sg, 2);
                sh += __shfl_xor_sync(0xffffffffu, sh, 1);
                sh += __shfl_xor_sync(0xffffffffu, sh, 2);
                if (tig == 0) {
                    part[cg * 128 + mt * 16 + g]     = sg;
                    part[cg * 128 + mt * 16 + 8 + g] = sh;
                }
            }
        }
        __syncthreads();

        // per-row score + online softmax (threads 0..127)
        if (tid < 128) {
            int grow = tbase + tid;
            if (grow < NROWS) {
                float s = b2v + part[tid] + part[128 + tid]
                              + part[256 + tid] + part[384 + tid];
                if (s > mx) {
                    float dd = fmaxf(mx - s, -87.f);
                    float e = expf(dd);
                    S1 = e * (S1 + dd * Z);
                    Z  = e * Z + 1.f;
                    mx = s;
                    arg = grow;
                } else {
                    float t = fmaxf(s - mx, -87.f);
                    float e = expf(t);
                    Z  += e;
                    S1 += t * e;
                }
            }
        }
        __syncthreads();
    }

    // block merge of per-thread softmax states (threads 0..127 hold state)
    float* smx = scratch;
    float* sZ  = scratch + 128;
    float* sS1 = scratch + 256;
    int*   sarg = (int*)(scratch + 384);
    if (tid < 128) { smx[tid] = mx; sZ[tid] = Z; sS1[tid] = S1; sarg[tid] = arg; }
    __syncthreads();
    for (int s = 64; s; s >>= 1) {
        if (tid < s) {
            float qm = smx[tid + s], qZ = sZ[tid + s], qS = sS1[tid + s];
            int   qa = sarg[tid + s];
            if (qm > smx[tid] || (qm == smx[tid] && qa < sarg[tid])) {
                float d = fmaxf(smx[tid] - qm, -87.f);
                float e = expf(d);
                float Zo = sZ[tid], S1o = sS1[tid];
                sZ[tid]  = qZ + e * Zo;
                sS1[tid] = qS + e * (S1o + d * Zo);
                smx[tid] = qm; sarg[tid] = qa;
            } else {
                float d = fmaxf(qm - smx[tid], -87.f);
                float e = expf(d);
                sZ[tid]  += e * qZ;
                sS1[tid] += e * (qS + d * qZ);
            }
        }
        __syncthreads();
    }
    if (tid == 0) {
        g_wmax[b] = smx[0];
        g_warg[b] = sarg[0];
        g_wZ[b]   = sZ[0];
        g_wS1[b]  = sS1[0];
    }

    // ================= grid barrier #2 + inline finalize ================
    grid_bar(tid);
    if (b != 0) return;

    float fmx = -3.402823466e38f, fZ = 0.f, fS1 = 0.f;
    int   farg = 0x7fffffff;
    if (tid < 128) {
        for (int i = tid; i < NWTOT; i += 128) {
            float qm = g_wmax[i], qZ = g_wZ[i], qS = g_wS1[i];
            int   qa = g_warg[i];
            if (qm > fmx || (qm == fmx && qa < farg)) {
                float d = fmaxf(fmx - qm, -87.f);
                float e = expf(d);
                float Zo = fZ, S1o = fS1;
                fZ  = qZ + e * Zo;
                fS1 = qS + e * (S1o + d * Zo);
                fmx = qm; farg = qa;
            } else {
                float d = fmaxf(qm - fmx, -87.f);
                float e = expf(d);
                fZ  += e * qZ;
                fS1 += e * (qS + d * qZ);
            }
        }
    }
    __syncthreads();
    if (tid < 128) { smx[tid] = fmx; sarg[tid] = farg; sZ[tid] = fZ; sS1[tid] = fS1; }
    __syncthreads();
    for (int s = 64; s; s >>= 1) {
        if (tid < s) {
            float qm = smx[tid + s], qZ = sZ[tid + s], qS = sS1[tid + s];
            int   qa = sarg[tid + s];
            if (qm > smx[tid] || (qm == smx[tid] && qa < sarg[tid])) {
                float d = fmaxf(smx[tid] - qm, -87.f);
                float e = expf(d);
                float Zo = sZ[tid], S1o = sS1[tid];
                sZ[tid]  = qZ + e * Zo;
                sS1[tid] = qS + e * (S1o + d * Zo);
                smx[tid] = qm; sarg[tid] = qa;
            } else {
                float d = fmaxf(qm - smx[tid], -87.f);
                float e = expf(d);
                sZ[tid]  += e * qZ;
                sS1[tid] += e * (qS + d * qZ);
            }
        }
        __syncthreads();
    }
    if (tid == 0) {
        float Zf = sZ[0], S1f = sS1[0];
        float logZ = logf(Zf);
        out[0] = (float)sarg[0];
        out[1] = 1.0f / Zf;          // p[idx]  (t=0 at argmax)
        out[2] = -logZ;              // logp[idx]
        out[3] = logZ - S1f / Zf;    // entropy
    }
}

// ---------------- launch ----------------
extern "C" void kernel_launch(void* const* d_in, const int* in_sizes, int n_in,
                              void* d_out, int out_size) {
    const float* x_graph = (const float*)d_in[0];
    const float* x_m     = (const float*)d_in[1];
    const float* x_job   = (const float*)d_in[2];
    const int*   m_ids   = (const int*)  d_in[3];
    const int*   job_idx = (const int*)  d_in[4];
    const float* W0      = (const float*)d_in[5];
    const float* b0      = (const float*)d_in[6];
    const float* W1      = (const float*)d_in[7];
    const float* b1      = (const float*)d_in[8];
    const float* W2      = (const float*)d_in[9];
    const float* b2      = (const float*)d_in[10];
    float* out = (float*)d_out;

    cudaFuncSetAttribute(score_kernel,
                         cudaFuncAttributeMaxDynamicSharedMemorySize, SMEM_SZ);

    score_kernel<<<SBLOCKS, 512, SMEM_SZ>>>(x_graph, x_m, x_job, W0, b0,
                                            m_ids, job_idx, W1, b1, W2, b2, out);
}